// round 14
// baseline (speedup 1.0000x reference)
#include <cuda_runtime.h>
#include <cuda_fp16.h>
#include <cstdint>

#define NPTS    131072
#define NBOOK   4
#define KCODES  1024
#define NCODES  4096
#define THREADS 256
#define CHUNK   32
#define CHUNKS  (NCODES / CHUNK)    // 128

// smem byte offsets (total 50KB)
#define SM_A    0               // 32KB A fp16 frags
#define SM_B    32768           // 2 x 8KB B fp16 frags
#define SM_EX   49152           // 2KB exchange
#define SMEM_TOTAL (49152 + 2048)

__device__ float g_csq[NCODES];
__device__ float g_rowsq[NPTS];
__device__ float g_maxcsq;
__device__ int   g_nflag;
__device__ int   g_flag[NPTS * NBOOK];
// B frags: [chunk(128)][n8grp(4)][ks(8)][lane(32)] -> {b0,b1} half2 pairs
__device__ uint2 g_bfh[CHUNKS * 4 * 8 * 32];

__device__ __forceinline__ bool lless(float v, int i, float v2, int i2) {
    return v < v2 || (v == v2 && i < i2);
}
__device__ __forceinline__ void upd(float& v1, int& i1, float& v2, int& i2,
                                    float s, int idx) {
    if (lless(s, idx, v1, i1)) { v2 = v1; i2 = i1; v1 = s; i1 = idx; }
    else if (lless(s, idx, v2, i2)) { v2 = s; i2 = idx; }
}
__device__ __forceinline__ void mrg(float& v1, int& i1, float& v2, int& i2,
                                    float ov1, int oi1, float ov2, int oi2) {
    if (lless(ov1, oi1, v1, i1)) {
        if (lless(v1, i1, ov2, oi2)) { v2 = v1; i2 = i1; }
        else { v2 = ov2; i2 = oi2; }
        v1 = ov1; i1 = oi1;
    } else if (lless(ov1, oi1, v2, i2)) { v2 = ov1; i2 = oi1; }
}
__device__ __forceinline__ void mma16(float* d, const uint32_t* a, const uint32_t* b) {
    asm volatile(
        "mma.sync.aligned.m16n8k16.row.col.f32.f16.f16.f32 "
        "{%0,%1,%2,%3}, {%4,%5,%6,%7}, {%8,%9}, {%0,%1,%2,%3};"
        : "+f"(d[0]), "+f"(d[1]), "+f"(d[2]), "+f"(d[3])
        : "r"(a[0]), "r"(a[1]), "r"(a[2]), "r"(a[3]), "r"(b[0]), "r"(b[1]));
}
__device__ __forceinline__ uint32_t smem_u32(const void* p) {
    return (uint32_t)__cvta_generic_to_shared(p);
}
__device__ __forceinline__ void cp16(uint32_t dst, const void* src) {
    asm volatile("cp.async.cg.shared.global [%0], [%1], 16;" :: "r"(dst), "l"(src));
}
__device__ __forceinline__ void cp_commit() { asm volatile("cp.async.commit_group;"); }
__device__ __forceinline__ void cp_wait()   { asm volatile("cp.async.wait_group 0;"); }
__device__ __forceinline__ uint32_t pack2(float a, float b) {
    __half2 h = __halves2half2(__float2half_rn(a), __float2half_rn(b));
    return *reinterpret_cast<uint32_t*>(&h);
}

// ||c||^2 for all 4096 codes. One warp per code.
__global__ void csq_kernel(const float* __restrict__ cb) {
    int warp = threadIdx.x >> 5, lane = threadIdx.x & 31;
    int code = blockIdx.x * 8 + warp;
    float4 v = reinterpret_cast<const float4*>(cb)[code * 32 + lane];
    float s = v.x * v.x + v.y * v.y + v.z * v.z + v.w * v.w;
#pragma unroll
    for (int o = 16; o > 0; o >>= 1) s += __shfl_xor_sync(0xffffffffu, s, o);
    if (lane == 0) g_csq[code] = s;
}

// max(csq) + reset flag counter (single block; runs after csq_kernel).
__global__ void prep2_kernel() {
    __shared__ float red[256];
    float m = 0.0f;
    for (int i = threadIdx.x; i < NCODES; i += 256) m = fmaxf(m, g_csq[i]);
    red[threadIdx.x] = m;
    __syncthreads();
    for (int o = 128; o > 0; o >>= 1) {
        if (threadIdx.x < o) red[threadIdx.x] = fmaxf(red[threadIdx.x], red[threadIdx.x + o]);
        __syncthreads();
    }
    if (threadIdx.x == 0) { g_maxcsq = red[0]; g_nflag = 0; }
}

// ||x||^2 per row. One warp per row.
__global__ void rowsq_kernel(const float* __restrict__ x) {
    int warp = threadIdx.x >> 5, lane = threadIdx.x & 31;
    int row = blockIdx.x * 8 + warp;
    float4 v = reinterpret_cast<const float4*>(x)[(size_t)row * 32 + lane];
    float s = v.x * v.x + v.y * v.y + v.z * v.z + v.w * v.w;
#pragma unroll
    for (int o = 16; o > 0; o >>= 1) s += __shfl_xor_sync(0xffffffffu, s, o);
    if (lane == 0) g_rowsq[row] = s;
}

// Pre-pack B into fp16 mma fragments.
__global__ void bsplit_kernel(const float* __restrict__ cb) {
    int idx = blockIdx.x * 256 + threadIdx.x;      // 131072 total
    int lane = idx & 31;
    int ks   = (idx >> 5) & 7;
    int grp  = (idx >> 8) & 3;
    int chunk = idx >> 10;
    int code = chunk * CHUNK + grp * 8 + (lane >> 2);
    const float* cr = cb + (size_t)code * 128 + ks * 16 + (lane & 3) * 2;
    g_bfh[idx] = make_uint2(pack2(cr[0], cr[1]), pack2(cr[8], cr[9]));
}

extern __shared__ char smem[];

__global__ void __launch_bounds__(THREADS, 3)
rqk_mma(const float* __restrict__ x, float* __restrict__ out) {
    const int tid  = threadIdx.x;
    const int lane = tid & 31;
    const int warp = tid >> 5;
    const int rr   = warp & 3;     // rows rr*32..+31 (two m16 tiles)
    const int cc   = warp >> 2;    // codes cc*16..+15 (two n8 frags)
    const int grp  = lane >> 4;    // unused granularity below
    const int qgrp = lane >> 2;
    const int th   = lane & 3;
    const int row0 = blockIdx.x * 128;

    float4* EX = reinterpret_cast<float4*>(smem + SM_EX);

    // ---- A setup: load rows, fp16 pack, store m16n8k16 frag-major ----
    {
        const float4* x4 = reinterpret_cast<const float4*>(x) + (size_t)row0 * 32;
#pragma unroll
        for (int it = 0; it < 16; ++it) {
            int u = it * 256 + tid;
            int row = u >> 5, k4 = u & 31;
            float4 q = x4[row * 32 + k4];
            int tile = row >> 4, r = row & 15;
            float e[4] = {q.x, q.y, q.z, q.w};
#pragma unroll
            for (int j = 0; j < 4; ++j) {
                int k = k4 * 4 + j;
                int ks = k >> 4, kk = k & 15;
                int reg = ((kk >> 3) << 1) | (r >> 3);
                int ln  = (r & 7) * 4 + ((kk & 7) >> 1);
                int off = (((tile * 8 + ks) * 32 + ln) << 4) + (reg << 2) + ((kk & 1) << 1);
                *reinterpret_cast<__half*>(smem + SM_A + off) = __float2half_rn(e[j]);
            }
        }
    }

    // ---- prefetch chunk 0 B frags (8KB) ----
    {
        uint32_t dst = smem_u32(smem + SM_B);
#pragma unroll
        for (int i = 0; i < 2; ++i)
            cp16(dst + (i * 256 + tid) * 16, g_bfh + (i * 256 + tid) * 2);
        cp_commit();
    }
    cp_wait();
    __syncthreads();

    float b1v[4], b2v[4];
    int   b1i[4], b2i[4];
#pragma unroll
    for (int i = 0; i < 4; ++i) { b1v[i] = 3.4e38f; b2v[i] = 3.4e38f;
                                  b1i[i] = 1 << 30; b2i[i] = 1 << 30; }

    const float maxcsq = g_maxcsq;

    for (int ch = 0; ch < CHUNKS; ++ch) {
        if (ch + 1 < CHUNKS) {
            uint32_t dst = smem_u32(smem + SM_B + ((ch + 1) & 1) * 8192);
            const uint2* src = g_bfh + (size_t)(ch + 1) * 1024;
#pragma unroll
            for (int i = 0; i < 2; ++i)
                cp16(dst + (i * 256 + tid) * 16, src + (i * 256 + tid) * 2);
            cp_commit();
        }

        const char* Bb = smem + SM_B + (ch & 1) * 8192;
        float acc[2][2][4];
#pragma unroll
        for (int mt = 0; mt < 2; ++mt)
#pragma unroll
            for (int nt = 0; nt < 2; ++nt)
#pragma unroll
                for (int r = 0; r < 4; ++r) acc[mt][nt][r] = 0.0f;

#pragma unroll
        for (int ks = 0; ks < 8; ++ks) {
            uint4 a0 = *reinterpret_cast<const uint4*>(
                smem + SM_A + (((rr * 2 + 0) * 8 + ks) * 32 + lane) * 16);
            uint4 a1 = *reinterpret_cast<const uint4*>(
                smem + SM_A + (((rr * 2 + 1) * 8 + ks) * 32 + lane) * 16);
            uint2 q0 = *reinterpret_cast<const uint2*>(
                Bb + (((cc * 2 + 0) * 8 + ks) * 32 + lane) * 8);
            uint2 q1 = *reinterpret_cast<const uint2*>(
                Bb + (((cc * 2 + 1) * 8 + ks) * 32 + lane) * 8);
            uint32_t b0[2] = {q0.x, q0.y}, b1[2] = {q1.x, q1.y};
            const uint32_t* A0 = reinterpret_cast<const uint32_t*>(&a0);
            const uint32_t* A1 = reinterpret_cast<const uint32_t*>(&a1);
            mma16(acc[0][0], A0, b0); mma16(acc[1][0], A1, b0);
            mma16(acc[0][1], A0, b1); mma16(acc[1][1], A1, b1);
        }

        // ---- epilogue: score = csq - 2*dot, per-row (best, second) ----
        int ib = (ch & 31) * CHUNK;
#pragma unroll
        for (int nt = 0; nt < 2; ++nt) {
            int n0 = cc * 16 + nt * 8 + th * 2;
            float cs0 = __ldg(&g_csq[ch * CHUNK + n0]);
            float cs1 = __ldg(&g_csq[ch * CHUNK + n0 + 1]);
            int id0 = ib + n0, id1 = id0 + 1;
#pragma unroll
            for (int mt = 0; mt < 2; ++mt)
#pragma unroll
                for (int h = 0; h < 2; ++h) {
                    int rid = mt * 2 + h;
                    float s0 = fmaf(-2.0f, acc[mt][nt][h * 2],     cs0);
                    float s1 = fmaf(-2.0f, acc[mt][nt][h * 2 + 1], cs1);
                    upd(b1v[rid], b1i[rid], b2v[rid], b2i[rid], s0, id0);
                    upd(b1v[rid], b1i[rid], b2v[rid], b2i[rid], s1, id1);
                }
        }

        // ---- book end: reduce lane quads, then across cc warps ----
        if ((ch & 31) == 31) {
            int book = ch >> 5;
#pragma unroll
            for (int rid = 0; rid < 4; ++rid) {
                float v1 = b1v[rid], v2 = b2v[rid];
                int   i1 = b1i[rid], i2 = b2i[rid];
#pragma unroll
                for (int off = 1; off < 4; off <<= 1) {
                    float ov1 = __shfl_xor_sync(0xffffffffu, v1, off);
                    int   oi1 = __shfl_xor_sync(0xffffffffu, i1, off);
                    float ov2 = __shfl_xor_sync(0xffffffffu, v2, off);
                    int   oi2 = __shfl_xor_sync(0xffffffffu, i2, off);
                    mrg(v1, i1, v2, i2, ov1, oi1, ov2, oi2);
                }
                b1v[rid] = v1; b1i[rid] = i1; b2v[rid] = v2; b2i[rid] = i2;
            }
            if (cc == 1 && th == 0) {
#pragma unroll
                for (int rid = 0; rid < 4; ++rid) {
                    int row = rr * 32 + (rid >> 1) * 16 + qgrp + (rid & 1) * 8;
                    EX[row] = make_float4(b1v[rid], __int_as_float(b1i[rid]),
                                          b2v[rid], __int_as_float(b2i[rid]));
                }
            }
            __syncthreads();
            if (cc == 0 && th == 0) {
#pragma unroll
                for (int rid = 0; rid < 4; ++rid) {
                    int row = rr * 32 + (rid >> 1) * 16 + qgrp + (rid & 1) * 8;
                    float4 o = EX[row];
                    float v1 = b1v[rid], v2 = b2v[rid];
                    int   i1 = b1i[rid], i2 = b2i[rid];
                    mrg(v1, i1, v2, i2, o.x, __float_as_int(o.y),
                        o.z, __float_as_int(o.w));
                    size_t oi = (size_t)(row0 + row) * NBOOK + book;
                    out[oi] = (float)i1;
                    // Rigorous flag: fp16 score error <= S/512 with
                    // S = sqrt(rowsq*maxcsq) (Cauchy-Schwarz). Flag margin < 2x
                    // bound with extra 2x safety + additive slack.
                    float S2 = __ldg(&g_rowsq[row0 + row]) * maxcsq;
                    float T = sqrtf(S2) * (1.0f / 128.0f) + 1e-2f;
                    if (v2 - v1 < T) {
                        int slot = atomicAdd(&g_nflag, 1);
                        g_flag[slot] = (int)oi;
                    }
                }
            }
#pragma unroll
            for (int i = 0; i < 4; ++i) { b1v[i] = 3.4e38f; b2v[i] = 3.4e38f;
                                          b1i[i] = 1 << 30; b2i[i] = 1 << 30; }
        }

        cp_wait();
        __syncthreads();
    }
}

// Exact fp32 full rescan of flagged (row,book) items. Warp per item,
// grid-stride over the compacted list.
__global__ void recheck_kernel(const float* __restrict__ x,
                               const float* __restrict__ cb,
                               float* __restrict__ out) {
    int nwarps = gridDim.x * (blockDim.x >> 5);
    int gw = blockIdx.x * (blockDim.x >> 5) + (threadIdx.x >> 5);
    int lane = threadIdx.x & 31;
    int n = g_nflag;
    for (int it = gw; it < n; it += nwarps) {
        int w = g_flag[it];
        int row = w >> 2, book = w & 3;
        const float4* xr = reinterpret_cast<const float4*>(x) + (size_t)row * 32;
        float bv = 3.4e38f; int bi = 1 << 30;
        for (int j = 0; j < 32; ++j) {
            int code = j * 32 + lane;
            const float4* cr = reinterpret_cast<const float4*>(cb) +
                               ((size_t)book * KCODES + code) * 32;
            float d = 0.0f;
#pragma unroll 8
            for (int k4 = 0; k4 < 32; ++k4) {
                float4 a = xr[k4], c = cr[k4];
                d = fmaf(a.x, c.x, d); d = fmaf(a.y, c.y, d);
                d = fmaf(a.z, c.z, d); d = fmaf(a.w, c.w, d);
            }
            float s = fmaf(-2.0f, d, g_csq[book * KCODES + code]);
            if (lless(s, code, bv, bi)) { bv = s; bi = code; }
        }
#pragma unroll
        for (int off = 16; off > 0; off >>= 1) {
            float ov = __shfl_xor_sync(0xffffffffu, bv, off);
            int   oi = __shfl_xor_sync(0xffffffffu, bi, off);
            if (lless(ov, oi, bv, bi)) { bv = ov; bi = oi; }
        }
        if (lane == 0) out[w] = (float)bi;
    }
}

extern "C" void kernel_launch(void* const* d_in, const int* in_sizes, int n_in,
                              void* d_out, int out_size) {
    const float* x  = nullptr;
    const float* cb = nullptr;
    for (int i = 0; i < n_in; ++i) {
        long long s = in_sizes[i];
        if (s == 16777216LL || s == 67108864LL) x  = (const float*)d_in[i];
        if (s == 524288LL   || s == 2097152LL)  cb = (const float*)d_in[i];
    }
    if (!x)  x  = (const float*)d_in[0];
    if (!cb) cb = (const float*)d_in[n_in > 1 ? 1 : 0];
    float* out = (float*)d_out;

    csq_kernel<<<NCODES / 8, 256>>>(cb);
    prep2_kernel<<<1, 256>>>();
    bsplit_kernel<<<(CHUNKS * 4 * 8 * 32) / 256, 256>>>(cb);
    rowsq_kernel<<<NPTS / 8, 256>>>(x);

    cudaFuncSetAttribute(rqk_mma, cudaFuncAttributeMaxDynamicSharedMemorySize,
                         SMEM_TOTAL);
    rqk_mma<<<NPTS / 128, THREADS, SMEM_TOTAL>>>(x, out);

    recheck_kernel<<<1024, 256>>>(x, cb, out);
}

// round 15
// speedup vs baseline: 7.0593x; 7.0593x over previous
#include <cuda_runtime.h>
#include <cuda_fp16.h>
#include <cstdint>

#define NPTS    131072
#define NBOOK   4
#define KCODES  1024
#define NCODES  4096
#define THREADS 256
#define CHUNK   32
#define CHUNKS  (NCODES / CHUNK)    // 128

// smem byte offsets (total 52KB)
#define SM_A    0               // 32KB A fp16 frags
#define SM_B    32768           // 2 x 8KB B fp16 frags
#define SM_EX   49152           // 4KB exchange (128 rows x 8 floats)
#define SMEM_TOTAL (49152 + 4096)

__device__ float g_csq[NCODES];
__device__ float g_rowsq[NPTS];
__device__ float g_maxcsq;
__device__ int   g_npair;
__device__ int   g_nfull;
__device__ int   g_pair[NPTS * NBOOK];
__device__ int   g_full[NPTS * NBOOK];
__device__ int   g_sec[NPTS * NBOOK];
// B frags: [chunk(128)][n8grp(4)][ks(8)][lane(32)] -> {b0,b1} half2 pairs
__device__ uint2 g_bfh[CHUNKS * 4 * 8 * 32];

__device__ __forceinline__ bool lless(float v, int i, float v2, int i2) {
    return v < v2 || (v == v2 && i < i2);
}
// top-3 insert with lowest-index tie-break
__device__ __forceinline__ void upd3(float& v1, int& i1, float& v2, int& i2,
                                     float& v3, int& i3, float s, int idx) {
    if (lless(s, idx, v1, i1)) {
        v3 = v2; i3 = i2; v2 = v1; i2 = i1; v1 = s; i1 = idx;
    } else if (lless(s, idx, v2, i2)) {
        v3 = v2; i3 = i2; v2 = s; i2 = idx;
    } else if (lless(s, idx, v3, i3)) {
        v3 = s; i3 = idx;
    }
}
__device__ __forceinline__ void mma16(float* d, const uint32_t* a, const uint32_t* b) {
    asm volatile(
        "mma.sync.aligned.m16n8k16.row.col.f32.f16.f16.f32 "
        "{%0,%1,%2,%3}, {%4,%5,%6,%7}, {%8,%9}, {%0,%1,%2,%3};"
        : "+f"(d[0]), "+f"(d[1]), "+f"(d[2]), "+f"(d[3])
        : "r"(a[0]), "r"(a[1]), "r"(a[2]), "r"(a[3]), "r"(b[0]), "r"(b[1]));
}
__device__ __forceinline__ uint32_t smem_u32(const void* p) {
    return (uint32_t)__cvta_generic_to_shared(p);
}
__device__ __forceinline__ void cp16(uint32_t dst, const void* src) {
    asm volatile("cp.async.cg.shared.global [%0], [%1], 16;" :: "r"(dst), "l"(src));
}
__device__ __forceinline__ void cp_commit() { asm volatile("cp.async.commit_group;"); }
__device__ __forceinline__ void cp_wait()   { asm volatile("cp.async.wait_group 0;"); }
__device__ __forceinline__ uint32_t pack2(float a, float b) {
    __half2 h = __halves2half2(__float2half_rn(a), __float2half_rn(b));
    return *reinterpret_cast<uint32_t*>(&h);
}

// ||c||^2 for all 4096 codes. One warp per code.
__global__ void csq_kernel(const float* __restrict__ cb) {
    int warp = threadIdx.x >> 5, lane = threadIdx.x & 31;
    int code = blockIdx.x * 8 + warp;
    float4 v = reinterpret_cast<const float4*>(cb)[code * 32 + lane];
    float s = v.x * v.x + v.y * v.y + v.z * v.z + v.w * v.w;
#pragma unroll
    for (int o = 16; o > 0; o >>= 1) s += __shfl_xor_sync(0xffffffffu, s, o);
    if (lane == 0) g_csq[code] = s;
}

// max(csq) + reset flag counters (single block; runs after csq_kernel).
__global__ void prep2_kernel() {
    __shared__ float red[256];
    float m = 0.0f;
    for (int i = threadIdx.x; i < NCODES; i += 256) m = fmaxf(m, g_csq[i]);
    red[threadIdx.x] = m;
    __syncthreads();
    for (int o = 128; o > 0; o >>= 1) {
        if (threadIdx.x < o) red[threadIdx.x] = fmaxf(red[threadIdx.x], red[threadIdx.x + o]);
        __syncthreads();
    }
    if (threadIdx.x == 0) { g_maxcsq = red[0]; g_npair = 0; g_nfull = 0; }
}

// ||x||^2 per row. One warp per row.
__global__ void rowsq_kernel(const float* __restrict__ x) {
    int warp = threadIdx.x >> 5, lane = threadIdx.x & 31;
    int row = blockIdx.x * 8 + warp;
    float4 v = reinterpret_cast<const float4*>(x)[(size_t)row * 32 + lane];
    float s = v.x * v.x + v.y * v.y + v.z * v.z + v.w * v.w;
#pragma unroll
    for (int o = 16; o > 0; o >>= 1) s += __shfl_xor_sync(0xffffffffu, s, o);
    if (lane == 0) g_rowsq[row] = s;
}

// Pre-pack B into fp16 mma fragments.
__global__ void bsplit_kernel(const float* __restrict__ cb) {
    int idx = blockIdx.x * 256 + threadIdx.x;      // 131072 total
    int lane = idx & 31;
    int ks   = (idx >> 5) & 7;
    int grp  = (idx >> 8) & 3;
    int chunk = idx >> 10;
    int code = chunk * CHUNK + grp * 8 + (lane >> 2);
    const float* cr = cb + (size_t)code * 128 + ks * 16 + (lane & 3) * 2;
    g_bfh[idx] = make_uint2(pack2(cr[0], cr[1]), pack2(cr[8], cr[9]));
}

extern __shared__ char smem[];

__global__ void __launch_bounds__(THREADS, 3)
rqk_mma(const float* __restrict__ x, float* __restrict__ out) {
    const int tid  = threadIdx.x;
    const int lane = tid & 31;
    const int warp = tid >> 5;
    const int rr   = warp & 3;     // rows rr*32..+31 (two m16 tiles)
    const int cc   = warp >> 2;    // codes cc*16..+15 (two n8 frags)
    const int qgrp = lane >> 2;
    const int th   = lane & 3;
    const int row0 = blockIdx.x * 128;

    float* EX = reinterpret_cast<float*>(smem + SM_EX);   // 8 floats per row

    // ---- A setup: load rows, fp16 pack, store m16n8k16 frag-major ----
    {
        const float4* x4 = reinterpret_cast<const float4*>(x) + (size_t)row0 * 32;
#pragma unroll
        for (int it = 0; it < 16; ++it) {
            int u = it * 256 + tid;
            int row = u >> 5, k4 = u & 31;
            float4 q = x4[row * 32 + k4];
            int tile = row >> 4, r = row & 15;
            float e[4] = {q.x, q.y, q.z, q.w};
#pragma unroll
            for (int j = 0; j < 4; ++j) {
                int k = k4 * 4 + j;
                int ks = k >> 4, kk = k & 15;
                int reg = ((kk >> 3) << 1) | (r >> 3);
                int ln  = (r & 7) * 4 + ((kk & 7) >> 1);
                int off = (((tile * 8 + ks) * 32 + ln) << 4) + (reg << 2) + ((kk & 1) << 1);
                *reinterpret_cast<__half*>(smem + SM_A + off) = __float2half_rn(e[j]);
            }
        }
    }

    // ---- prefetch chunk 0 B frags (8KB) ----
    {
        uint32_t dst = smem_u32(smem + SM_B);
#pragma unroll
        for (int i = 0; i < 2; ++i)
            cp16(dst + (i * 256 + tid) * 16, g_bfh + (i * 256 + tid) * 2);
        cp_commit();
    }
    cp_wait();
    __syncthreads();

    float b1v[4], b2v[4], b3v[4];
    int   b1i[4], b2i[4], b3i[4];
#pragma unroll
    for (int i = 0; i < 4; ++i) {
        b1v[i] = 3.4e38f; b2v[i] = 3.4e38f; b3v[i] = 3.4e38f;
        b1i[i] = 1 << 30; b2i[i] = 1 << 30; b3i[i] = 1 << 30;
    }

    const float maxcsq = g_maxcsq;

    for (int ch = 0; ch < CHUNKS; ++ch) {
        if (ch + 1 < CHUNKS) {
            uint32_t dst = smem_u32(smem + SM_B + ((ch + 1) & 1) * 8192);
            const uint2* src = g_bfh + (size_t)(ch + 1) * 1024;
#pragma unroll
            for (int i = 0; i < 2; ++i)
                cp16(dst + (i * 256 + tid) * 16, src + (i * 256 + tid) * 2);
            cp_commit();
        }

        const char* Bb = smem + SM_B + (ch & 1) * 8192;
        float acc[2][2][4];
#pragma unroll
        for (int mt = 0; mt < 2; ++mt)
#pragma unroll
            for (int nt = 0; nt < 2; ++nt)
#pragma unroll
                for (int r = 0; r < 4; ++r) acc[mt][nt][r] = 0.0f;

#pragma unroll
        for (int ks = 0; ks < 8; ++ks) {
            uint4 a0 = *reinterpret_cast<const uint4*>(
                smem + SM_A + (((rr * 2 + 0) * 8 + ks) * 32 + lane) * 16);
            uint4 a1 = *reinterpret_cast<const uint4*>(
                smem + SM_A + (((rr * 2 + 1) * 8 + ks) * 32 + lane) * 16);
            uint2 q0 = *reinterpret_cast<const uint2*>(
                Bb + (((cc * 2 + 0) * 8 + ks) * 32 + lane) * 8);
            uint2 q1 = *reinterpret_cast<const uint2*>(
                Bb + (((cc * 2 + 1) * 8 + ks) * 32 + lane) * 8);
            uint32_t b0[2] = {q0.x, q0.y}, b1[2] = {q1.x, q1.y};
            const uint32_t* A0 = reinterpret_cast<const uint32_t*>(&a0);
            const uint32_t* A1 = reinterpret_cast<const uint32_t*>(&a1);
            mma16(acc[0][0], A0, b0); mma16(acc[1][0], A1, b0);
            mma16(acc[0][1], A0, b1); mma16(acc[1][1], A1, b1);
        }

        // ---- epilogue: score = csq - 2*dot, per-row top-3 ----
        int ib = (ch & 31) * CHUNK;
#pragma unroll
        for (int nt = 0; nt < 2; ++nt) {
            int n0 = cc * 16 + nt * 8 + th * 2;
            float cs0 = __ldg(&g_csq[ch * CHUNK + n0]);
            float cs1 = __ldg(&g_csq[ch * CHUNK + n0 + 1]);
            int id0 = ib + n0, id1 = id0 + 1;
#pragma unroll
            for (int mt = 0; mt < 2; ++mt)
#pragma unroll
                for (int h = 0; h < 2; ++h) {
                    int rid = mt * 2 + h;
                    float s0 = fmaf(-2.0f, acc[mt][nt][h * 2],     cs0);
                    float s1 = fmaf(-2.0f, acc[mt][nt][h * 2 + 1], cs1);
                    upd3(b1v[rid], b1i[rid], b2v[rid], b2i[rid],
                         b3v[rid], b3i[rid], s0, id0);
                    upd3(b1v[rid], b1i[rid], b2v[rid], b2i[rid],
                         b3v[rid], b3i[rid], s1, id1);
                }
        }

        // ---- book end: reduce lane quads, then across cc warps ----
        if ((ch & 31) == 31) {
            int book = ch >> 5;
#pragma unroll
            for (int rid = 0; rid < 4; ++rid) {
                float v1 = b1v[rid], v2 = b2v[rid], v3 = b3v[rid];
                int   i1 = b1i[rid], i2 = b2i[rid], i3 = b3i[rid];
#pragma unroll
                for (int off = 1; off < 4; off <<= 1) {
                    float ov1 = __shfl_xor_sync(0xffffffffu, v1, off);
                    int   oi1 = __shfl_xor_sync(0xffffffffu, i1, off);
                    float ov2 = __shfl_xor_sync(0xffffffffu, v2, off);
                    int   oi2 = __shfl_xor_sync(0xffffffffu, i2, off);
                    float ov3 = __shfl_xor_sync(0xffffffffu, v3, off);
                    int   oi3 = __shfl_xor_sync(0xffffffffu, i3, off);
                    upd3(v1, i1, v2, i2, v3, i3, ov1, oi1);
                    upd3(v1, i1, v2, i2, v3, i3, ov2, oi2);
                    upd3(v1, i1, v2, i2, v3, i3, ov3, oi3);
                }
                b1v[rid] = v1; b1i[rid] = i1; b2v[rid] = v2; b2i[rid] = i2;
                b3v[rid] = v3; b3i[rid] = i3;
            }
            if (cc == 1 && th == 0) {
#pragma unroll
                for (int rid = 0; rid < 4; ++rid) {
                    int row = rr * 32 + (rid >> 1) * 16 + qgrp + (rid & 1) * 8;
                    float* e = EX + row * 8;
                    e[0] = b1v[rid]; e[1] = __int_as_float(b1i[rid]);
                    e[2] = b2v[rid]; e[3] = __int_as_float(b2i[rid]);
                    e[4] = b3v[rid]; e[5] = __int_as_float(b3i[rid]);
                }
            }
            __syncthreads();
            if (cc == 0 && th == 0) {
#pragma unroll
                for (int rid = 0; rid < 4; ++rid) {
                    int row = rr * 32 + (rid >> 1) * 16 + qgrp + (rid & 1) * 8;
                    const float* e = EX + row * 8;
                    float v1 = b1v[rid], v2 = b2v[rid], v3 = b3v[rid];
                    int   i1 = b1i[rid], i2 = b2i[rid], i3 = b3i[rid];
                    upd3(v1, i1, v2, i2, v3, i3, e[0], __float_as_int(e[1]));
                    upd3(v1, i1, v2, i2, v3, i3, e[2], __float_as_int(e[3]));
                    upd3(v1, i1, v2, i2, v3, i3, e[4], __float_as_int(e[5]));
                    size_t oi = (size_t)(row0 + row) * NBOOK + book;
                    out[oi] = (float)i1;
                    // T >= 2*eps: eps <= 2^-9*sqrt(rowsq*maxcsq) fp16 input
                    // rounding (Cauchy-Schwarz) + slack for fp32 accum.
                    float S2 = __ldg(&g_rowsq[row0 + row]) * maxcsq;
                    float T = sqrtf(S2) * (1.0f / 256.0f) + 1e-2f;
                    if (v3 - v1 < T) {
                        int slot = atomicAdd(&g_nfull, 1);
                        g_full[slot] = (int)oi;
                    } else if (v2 - v1 < T) {
                        g_sec[oi] = i2;
                        int slot = atomicAdd(&g_npair, 1);
                        g_pair[slot] = (int)oi;
                    }
                }
            }
#pragma unroll
            for (int i = 0; i < 4; ++i) {
                b1v[i] = 3.4e38f; b2v[i] = 3.4e38f; b3v[i] = 3.4e38f;
                b1i[i] = 1 << 30; b2i[i] = 1 << 30; b3i[i] = 1 << 30;
            }
        }

        cp_wait();
        __syncthreads();
    }
}

// Exact fp32 compare of the approx top-2 (winner provably among them).
__global__ void pairfix_kernel(const float* __restrict__ x,
                               const float* __restrict__ cb,
                               float* __restrict__ out) {
    int nwarps = gridDim.x * (blockDim.x >> 5);
    int gw = blockIdx.x * (blockDim.x >> 5) + (threadIdx.x >> 5);
    int lane = threadIdx.x & 31;
    int n = g_npair;
    for (int it = gw; it < n; it += nwarps) {
        int w = g_pair[it];
        int row = w >> 2, book = w & 3;
        int i1 = (int)out[w];
        int i2 = g_sec[w];
        float4 a = reinterpret_cast<const float4*>(x)[(size_t)row * 32 + lane];
        float4 c1 = reinterpret_cast<const float4*>(cb)[
            ((size_t)book * KCODES + i1) * 32 + lane];
        float4 c2 = reinterpret_cast<const float4*>(cb)[
            ((size_t)book * KCODES + i2) * 32 + lane];
        float d1 = a.x * c1.x + a.y * c1.y + a.z * c1.z + a.w * c1.w;
        float d2 = a.x * c2.x + a.y * c2.y + a.z * c2.z + a.w * c2.w;
#pragma unroll
        for (int o = 16; o > 0; o >>= 1) {
            d1 += __shfl_xor_sync(0xffffffffu, d1, o);
            d2 += __shfl_xor_sync(0xffffffffu, d2, o);
        }
        if (lane == 0) {
            float s1 = fmaf(-2.0f, d1, g_csq[book * KCODES + i1]);
            float s2 = fmaf(-2.0f, d2, g_csq[book * KCODES + i2]);
            out[w] = (float)(lless(s2, i2, s1, i1) ? i2 : i1);
        }
    }
}

// Full exact fp32 rescan of items where top-3 margin was too tight.
__global__ void recheck_kernel(const float* __restrict__ x,
                               const float* __restrict__ cb,
                               float* __restrict__ out) {
    int nwarps = gridDim.x * (blockDim.x >> 5);
    int gw = blockIdx.x * (blockDim.x >> 5) + (threadIdx.x >> 5);
    int lane = threadIdx.x & 31;
    int n = g_nfull;
    for (int it = gw; it < n; it += nwarps) {
        int w = g_full[it];
        int row = w >> 2, book = w & 3;
        const float4* xr = reinterpret_cast<const float4*>(x) + (size_t)row * 32;
        float bv = 3.4e38f; int bi = 1 << 30;
        for (int j = 0; j < 32; ++j) {
            int code = j * 32 + lane;
            const float4* cr = reinterpret_cast<const float4*>(cb) +
                               ((size_t)book * KCODES + code) * 32;
            float d = 0.0f;
#pragma unroll 8
            for (int k4 = 0; k4 < 32; ++k4) {
                float4 a = xr[k4], c = cr[k4];
                d = fmaf(a.x, c.x, d); d = fmaf(a.y, c.y, d);
                d = fmaf(a.z, c.z, d); d = fmaf(a.w, c.w, d);
            }
            float s = fmaf(-2.0f, d, g_csq[book * KCODES + code]);
            if (lless(s, code, bv, bi)) { bv = s; bi = code; }
        }
#pragma unroll
        for (int off = 16; off > 0; off >>= 1) {
            float ov = __shfl_xor_sync(0xffffffffu, bv, off);
            int   oi = __shfl_xor_sync(0xffffffffu, bi, off);
            if (lless(ov, oi, bv, bi)) { bv = ov; bi = oi; }
        }
        if (lane == 0) out[w] = (float)bi;
    }
}

extern "C" void kernel_launch(void* const* d_in, const int* in_sizes, int n_in,
                              void* d_out, int out_size) {
    const float* x  = nullptr;
    const float* cb = nullptr;
    for (int i = 0; i < n_in; ++i) {
        long long s = in_sizes[i];
        if (s == 16777216LL || s == 67108864LL) x  = (const float*)d_in[i];
        if (s == 524288LL   || s == 2097152LL)  cb = (const float*)d_in[i];
    }
    if (!x)  x  = (const float*)d_in[0];
    if (!cb) cb = (const float*)d_in[n_in > 1 ? 1 : 0];
    float* out = (float*)d_out;

    csq_kernel<<<NCODES / 8, 256>>>(cb);
    prep2_kernel<<<1, 256>>>();
    bsplit_kernel<<<(CHUNKS * 4 * 8 * 32) / 256, 256>>>(cb);
    rowsq_kernel<<<NPTS / 8, 256>>>(x);

    cudaFuncSetAttribute(rqk_mma, cudaFuncAttributeMaxDynamicSharedMemorySize,
                         SMEM_TOTAL);
    rqk_mma<<<NPTS / 128, THREADS, SMEM_TOTAL>>>(x, out);

    pairfix_kernel<<<256, 256>>>(x, cb, out);
    recheck_kernel<<<1024, 256>>>(x, cb, out);
}

// round 16
// speedup vs baseline: 11.1242x; 1.5758x over previous
#include <cuda_runtime.h>
#include <cuda_fp16.h>
#include <cstdint>

#define NPTS    131072
#define NBOOK   4
#define KCODES  1024
#define NCODES  4096
#define THREADS 256
#define CHUNK   32
#define CHUNKS  (NCODES / CHUNK)    // 128

// smem byte offsets (total 50KB)
#define SM_A    0               // 32KB A fp16 frags
#define SM_B    32768           // 2 x 8KB B fp16 frags
#define SM_EX   49152           // 2KB exchange (128 rows x 4 uints)
#define SMEM_TOTAL (49152 + 2048)

__device__ float g_csq[NCODES];
__device__ float g_rowsq[NPTS];
__device__ float g_maxcsq;
__device__ int   g_npair;
__device__ int   g_nfull;
__device__ int   g_pair[NPTS * NBOOK];
__device__ int   g_full[NPTS * NBOOK];
__device__ int   g_sec[NPTS * NBOOK];
// B frags: [chunk(128)][n8grp(4)][ks(8)][lane(32)] -> {b0,b1} half2 pairs
__device__ uint2 g_bfh[CHUNKS * 4 * 8 * 32];

__device__ __forceinline__ bool lless(float v, int i, float v2, int i2) {
    return v < v2 || (v == v2 && i < i2);
}
// float -> order-preserving uint
__device__ __forceinline__ uint32_t ford(float s) {
    uint32_t b = __float_as_uint(s);
    return b ^ (uint32_t)(((int32_t)b >> 31) | 0x80000000);
}
// inverse (on quantized value)
__device__ __forceinline__ float funord(uint32_t u) {
    uint32_t q = u & 0xFFFFFC00u;
    uint32_t b = (q & 0x80000000u) ? (q ^ 0x80000000u) : ~q;
    return __uint_as_float(b);
}
// branch-free top-3 insert on packed (score|idx) uints
__device__ __forceinline__ void ins3(uint32_t& v1, uint32_t& v2, uint32_t& v3,
                                     uint32_t p) {
    uint32_t nv3 = (p < v2) ? v2 : ((p < v3) ? p : v3);
    uint32_t nv2 = (p < v1) ? v1 : ((p < v2) ? p : v2);
    v1 = (p < v1) ? p : v1;
    v2 = nv2; v3 = nv3;
}
__device__ __forceinline__ void mma16(float* d, const uint32_t* a, const uint32_t* b) {
    asm volatile(
        "mma.sync.aligned.m16n8k16.row.col.f32.f16.f16.f32 "
        "{%0,%1,%2,%3}, {%4,%5,%6,%7}, {%8,%9}, {%0,%1,%2,%3};"
        : "+f"(d[0]), "+f"(d[1]), "+f"(d[2]), "+f"(d[3])
        : "r"(a[0]), "r"(a[1]), "r"(a[2]), "r"(a[3]), "r"(b[0]), "r"(b[1]));
}
__device__ __forceinline__ uint32_t smem_u32(const void* p) {
    return (uint32_t)__cvta_generic_to_shared(p);
}
__device__ __forceinline__ void cp16(uint32_t dst, const void* src) {
    asm volatile("cp.async.cg.shared.global [%0], [%1], 16;" :: "r"(dst), "l"(src));
}
__device__ __forceinline__ void cp_commit() { asm volatile("cp.async.commit_group;"); }
__device__ __forceinline__ void cp_wait()   { asm volatile("cp.async.wait_group 0;"); }
__device__ __forceinline__ uint32_t pack2(float a, float b) {
    __half2 h = __halves2half2(__float2half_rn(a), __float2half_rn(b));
    return *reinterpret_cast<uint32_t*>(&h);
}

// ||c||^2 for all 4096 codes. One warp per code.
__global__ void csq_kernel(const float* __restrict__ cb) {
    int warp = threadIdx.x >> 5, lane = threadIdx.x & 31;
    int code = blockIdx.x * 8 + warp;
    float4 v = reinterpret_cast<const float4*>(cb)[code * 32 + lane];
    float s = v.x * v.x + v.y * v.y + v.z * v.z + v.w * v.w;
#pragma unroll
    for (int o = 16; o > 0; o >>= 1) s += __shfl_xor_sync(0xffffffffu, s, o);
    if (lane == 0) g_csq[code] = s;
}

// max(csq) + reset flag counters.
__global__ void prep2_kernel() {
    __shared__ float red[256];
    float m = 0.0f;
    for (int i = threadIdx.x; i < NCODES; i += 256) m = fmaxf(m, g_csq[i]);
    red[threadIdx.x] = m;
    __syncthreads();
    for (int o = 128; o > 0; o >>= 1) {
        if (threadIdx.x < o) red[threadIdx.x] = fmaxf(red[threadIdx.x], red[threadIdx.x + o]);
        __syncthreads();
    }
    if (threadIdx.x == 0) { g_maxcsq = red[0]; g_npair = 0; g_nfull = 0; }
}

// ||x||^2 per row. One warp per row.
__global__ void rowsq_kernel(const float* __restrict__ x) {
    int warp = threadIdx.x >> 5, lane = threadIdx.x & 31;
    int row = blockIdx.x * 8 + warp;
    float4 v = reinterpret_cast<const float4*>(x)[(size_t)row * 32 + lane];
    float s = v.x * v.x + v.y * v.y + v.z * v.z + v.w * v.w;
#pragma unroll
    for (int o = 16; o > 0; o >>= 1) s += __shfl_xor_sync(0xffffffffu, s, o);
    if (lane == 0) g_rowsq[row] = s;
}

// Pre-pack B into fp16 mma fragments.
__global__ void bsplit_kernel(const float* __restrict__ cb) {
    int idx = blockIdx.x * 256 + threadIdx.x;      // 131072 total
    int lane = idx & 31;
    int ks   = (idx >> 5) & 7;
    int grp  = (idx >> 8) & 3;
    int chunk = idx >> 10;
    int code = chunk * CHUNK + grp * 8 + (lane >> 2);
    const float* cr = cb + (size_t)code * 128 + ks * 16 + (lane & 3) * 2;
    g_bfh[idx] = make_uint2(pack2(cr[0], cr[1]), pack2(cr[8], cr[9]));
}

extern __shared__ char smem[];

__global__ void __launch_bounds__(THREADS, 3)
rqk_mma(const float* __restrict__ x, float* __restrict__ out) {
    const int tid  = threadIdx.x;
    const int lane = tid & 31;
    const int warp = tid >> 5;
    const int rr   = warp & 3;     // rows rr*32..+31 (two m16 tiles)
    const int cc   = warp >> 2;    // codes cc*16..+15 (two n8 frags)
    const int qgrp = lane >> 2;
    const int th   = lane & 3;
    const int row0 = blockIdx.x * 128;

    uint32_t* EX = reinterpret_cast<uint32_t*>(smem + SM_EX);  // 4 uints/row

    // ---- A setup: load rows, fp16 pack, store m16n8k16 frag-major ----
    {
        const float4* x4 = reinterpret_cast<const float4*>(x) + (size_t)row0 * 32;
#pragma unroll
        for (int it = 0; it < 16; ++it) {
            int u = it * 256 + tid;
            int row = u >> 5, k4 = u & 31;
            float4 q = x4[row * 32 + k4];
            int tile = row >> 4, r = row & 15;
            float e[4] = {q.x, q.y, q.z, q.w};
#pragma unroll
            for (int j = 0; j < 4; ++j) {
                int k = k4 * 4 + j;
                int ks = k >> 4, kk = k & 15;
                int reg = ((kk >> 3) << 1) | (r >> 3);
                int ln  = (r & 7) * 4 + ((kk & 7) >> 1);
                int off = (((tile * 8 + ks) * 32 + ln) << 4) + (reg << 2) + ((kk & 1) << 1);
                *reinterpret_cast<__half*>(smem + SM_A + off) = __float2half_rn(e[j]);
            }
        }
    }

    // ---- prefetch chunk 0 B frags (8KB) ----
    {
        uint32_t dst = smem_u32(smem + SM_B);
#pragma unroll
        for (int i = 0; i < 2; ++i)
            cp16(dst + (i * 256 + tid) * 16, g_bfh + (i * 256 + tid) * 2);
        cp_commit();
    }
    cp_wait();
    __syncthreads();

    uint32_t pk1[4], pk2[4], pk3[4];
#pragma unroll
    for (int i = 0; i < 4; ++i) { pk1[i] = 0xFFFFFFFFu; pk2[i] = 0xFFFFFFFFu;
                                  pk3[i] = 0xFFFFFFFFu; }

    const float maxcsq = g_maxcsq;

    for (int ch = 0; ch < CHUNKS; ++ch) {
        if (ch + 1 < CHUNKS) {
            uint32_t dst = smem_u32(smem + SM_B + ((ch + 1) & 1) * 8192);
            const uint2* src = g_bfh + (size_t)(ch + 1) * 1024;
#pragma unroll
            for (int i = 0; i < 2; ++i)
                cp16(dst + (i * 256 + tid) * 16, src + (i * 256 + tid) * 2);
            cp_commit();
        }

        const char* Bb = smem + SM_B + (ch & 1) * 8192;
        float acc[2][2][4];
#pragma unroll
        for (int mt = 0; mt < 2; ++mt)
#pragma unroll
            for (int nt = 0; nt < 2; ++nt)
#pragma unroll
                for (int r = 0; r < 4; ++r) acc[mt][nt][r] = 0.0f;

#pragma unroll
        for (int ks = 0; ks < 8; ++ks) {
            uint4 a0 = *reinterpret_cast<const uint4*>(
                smem + SM_A + (((rr * 2 + 0) * 8 + ks) * 32 + lane) * 16);
            uint4 a1 = *reinterpret_cast<const uint4*>(
                smem + SM_A + (((rr * 2 + 1) * 8 + ks) * 32 + lane) * 16);
            uint2 q0 = *reinterpret_cast<const uint2*>(
                Bb + (((cc * 2 + 0) * 8 + ks) * 32 + lane) * 8);
            uint2 q1 = *reinterpret_cast<const uint2*>(
                Bb + (((cc * 2 + 1) * 8 + ks) * 32 + lane) * 8);
            uint32_t b0[2] = {q0.x, q0.y}, b1[2] = {q1.x, q1.y};
            const uint32_t* A0 = reinterpret_cast<const uint32_t*>(&a0);
            const uint32_t* A1 = reinterpret_cast<const uint32_t*>(&a1);
            mma16(acc[0][0], A0, b0); mma16(acc[1][0], A1, b0);
            mma16(acc[0][1], A0, b1); mma16(acc[1][1], A1, b1);
        }

        // ---- epilogue: packed (score|idx) branch-free top-3 ----
        int ib = (ch & 31) * CHUNK;
#pragma unroll
        for (int nt = 0; nt < 2; ++nt) {
            int n0 = cc * 16 + nt * 8 + th * 2;
            float cs0 = __ldg(&g_csq[ch * CHUNK + n0]);
            float cs1 = __ldg(&g_csq[ch * CHUNK + n0 + 1]);
            uint32_t id0 = (uint32_t)(ib + n0), id1 = id0 + 1;
#pragma unroll
            for (int mt = 0; mt < 2; ++mt)
#pragma unroll
                for (int h = 0; h < 2; ++h) {
                    int rid = mt * 2 + h;
                    float s0 = fmaf(-2.0f, acc[mt][nt][h * 2],     cs0);
                    float s1 = fmaf(-2.0f, acc[mt][nt][h * 2 + 1], cs1);
                    uint32_t p0 = (ford(s0) & 0xFFFFFC00u) | id0;
                    uint32_t p1 = (ford(s1) & 0xFFFFFC00u) | id1;
                    ins3(pk1[rid], pk2[rid], pk3[rid], p0);
                    ins3(pk1[rid], pk2[rid], pk3[rid], p1);
                }
        }

        // ---- book end: reduce lane quads, then across cc warps ----
        if ((ch & 31) == 31) {
            int book = ch >> 5;
#pragma unroll
            for (int rid = 0; rid < 4; ++rid) {
                uint32_t v1 = pk1[rid], v2 = pk2[rid], v3 = pk3[rid];
#pragma unroll
                for (int off = 1; off < 4; off <<= 1) {
                    uint32_t o1 = __shfl_xor_sync(0xffffffffu, v1, off);
                    uint32_t o2 = __shfl_xor_sync(0xffffffffu, v2, off);
                    uint32_t o3 = __shfl_xor_sync(0xffffffffu, v3, off);
                    ins3(v1, v2, v3, o1);
                    ins3(v1, v2, v3, o2);
                    ins3(v1, v2, v3, o3);
                }
                pk1[rid] = v1; pk2[rid] = v2; pk3[rid] = v3;
            }
            if (cc == 1 && th == 0) {
#pragma unroll
                for (int rid = 0; rid < 4; ++rid) {
                    int row = rr * 32 + (rid >> 1) * 16 + qgrp + (rid & 1) * 8;
                    uint32_t* e = EX + row * 4;
                    e[0] = pk1[rid]; e[1] = pk2[rid]; e[2] = pk3[rid];
                }
            }
            __syncthreads();
            if (cc == 0 && th == 0) {
#pragma unroll
                for (int rid = 0; rid < 4; ++rid) {
                    int row = rr * 32 + (rid >> 1) * 16 + qgrp + (rid & 1) * 8;
                    const uint32_t* e = EX + row * 4;
                    uint32_t v1 = pk1[rid], v2 = pk2[rid], v3 = pk3[rid];
                    ins3(v1, v2, v3, e[0]);
                    ins3(v1, v2, v3, e[1]);
                    ins3(v1, v2, v3, e[2]);
                    size_t oi = (size_t)(row0 + row) * NBOOK + book;
                    uint32_t i1 = v1 & 0x3FFu;
                    out[oi] = (float)i1;
                    // T >= 2*eps + quantization slack. eps <= 2^-9*sqrt(S2)
                    // (fp16 input rounding, Cauchy-Schwarz); quantization of
                    // packed scores <= ~0.008 absolute each.
                    float S2 = __ldg(&g_rowsq[row0 + row]) * maxcsq;
                    float T = sqrtf(S2) * (1.0f / 256.0f) + 3e-2f;
                    float f1 = funord(v1), f2 = funord(v2), f3 = funord(v3);
                    if (f3 - f1 < T) {
                        int slot = atomicAdd(&g_nfull, 1);
                        g_full[slot] = (int)oi;
                    } else if (f2 - f1 < T) {
                        g_sec[oi] = (int)(v2 & 0x3FFu);
                        int slot = atomicAdd(&g_npair, 1);
                        g_pair[slot] = (int)oi;
                    }
                }
            }
#pragma unroll
            for (int i = 0; i < 4; ++i) { pk1[i] = 0xFFFFFFFFu;
                                          pk2[i] = 0xFFFFFFFFu;
                                          pk3[i] = 0xFFFFFFFFu; }
        }

        cp_wait();
        __syncthreads();
    }
}

// Exact fp32 compare of the approx top-2 (winner provably among them).
__global__ void pairfix_kernel(const float* __restrict__ x,
                               const float* __restrict__ cb,
                               float* __restrict__ out) {
    int nwarps = gridDim.x * (blockDim.x >> 5);
    int gw = blockIdx.x * (blockDim.x >> 5) + (threadIdx.x >> 5);
    int lane = threadIdx.x & 31;
    int n = g_npair;
    for (int it = gw; it < n; it += nwarps) {
        int w = g_pair[it];
        int row = w >> 2, book = w & 3;
        int i1 = (int)out[w];
        int i2 = g_sec[w];
        float4 a = reinterpret_cast<const float4*>(x)[(size_t)row * 32 + lane];
        float4 c1 = reinterpret_cast<const float4*>(cb)[
            ((size_t)book * KCODES + i1) * 32 + lane];
        float4 c2 = reinterpret_cast<const float4*>(cb)[
            ((size_t)book * KCODES + i2) * 32 + lane];
        float d1 = a.x * c1.x + a.y * c1.y + a.z * c1.z + a.w * c1.w;
        float d2 = a.x * c2.x + a.y * c2.y + a.z * c2.z + a.w * c2.w;
#pragma unroll
        for (int o = 16; o > 0; o >>= 1) {
            d1 += __shfl_xor_sync(0xffffffffu, d1, o);
            d2 += __shfl_xor_sync(0xffffffffu, d2, o);
        }
        if (lane == 0) {
            float s1 = fmaf(-2.0f, d1, g_csq[book * KCODES + i1]);
            float s2 = fmaf(-2.0f, d2, g_csq[book * KCODES + i2]);
            out[w] = (float)(lless(s2, i2, s1, i1) ? i2 : i1);
        }
    }
}

// Full exact fp32 rescan of items where top-3 margin was too tight.
__global__ void recheck_kernel(const float* __restrict__ x,
                               const float* __restrict__ cb,
                               float* __restrict__ out) {
    int nwarps = gridDim.x * (blockDim.x >> 5);
    int gw = blockIdx.x * (blockDim.x >> 5) + (threadIdx.x >> 5);
    int lane = threadIdx.x & 31;
    int n = g_nfull;
    for (int it = gw; it < n; it += nwarps) {
        int w = g_full[it];
        int row = w >> 2, book = w & 3;
        const float4* xr = reinterpret_cast<const float4*>(x) + (size_t)row * 32;
        float bv = 3.4e38f; int bi = 1 << 30;
        for (int j = 0; j < 32; ++j) {
            int code = j * 32 + lane;
            const float4* cr = reinterpret_cast<const float4*>(cb) +
                               ((size_t)book * KCODES + code) * 32;
            float d = 0.0f;
#pragma unroll 8
            for (int k4 = 0; k4 < 32; ++k4) {
                float4 a = xr[k4], c = cr[k4];
                d = fmaf(a.x, c.x, d); d = fmaf(a.y, c.y, d);
                d = fmaf(a.z, c.z, d); d = fmaf(a.w, c.w, d);
            }
            float s = fmaf(-2.0f, d, g_csq[book * KCODES + code]);
            if (lless(s, code, bv, bi)) { bv = s; bi = code; }
        }
#pragma unroll
        for (int off = 16; off > 0; off >>= 1) {
            float ov = __shfl_xor_sync(0xffffffffu, bv, off);
            int   oi = __shfl_xor_sync(0xffffffffu, bi, off);
            if (lless(ov, oi, bv, bi)) { bv = ov; bi = oi; }
        }
        if (lane == 0) out[w] = (float)bi;
    }
}

extern "C" void kernel_launch(void* const* d_in, const int* in_sizes, int n_in,
                              void* d_out, int out_size) {
    const float* x  = nullptr;
    const float* cb = nullptr;
    for (int i = 0; i < n_in; ++i) {
        long long s = in_sizes[i];
        if (s == 16777216LL || s == 67108864LL) x  = (const float*)d_in[i];
        if (s == 524288LL   || s == 2097152LL)  cb = (const float*)d_in[i];
    }
    if (!x)  x  = (const float*)d_in[0];
    if (!cb) cb = (const float*)d_in[n_in > 1 ? 1 : 0];
    float* out = (float*)d_out;

    csq_kernel<<<NCODES / 8, 256>>>(cb);
    prep2_kernel<<<1, 256>>>();
    bsplit_kernel<<<(CHUNKS * 4 * 8 * 32) / 256, 256>>>(cb);
    rowsq_kernel<<<NPTS / 8, 256>>>(x);

    cudaFuncSetAttribute(rqk_mma, cudaFuncAttributeMaxDynamicSharedMemorySize,
                         SMEM_TOTAL);
    rqk_mma<<<NPTS / 128, THREADS, SMEM_TOTAL>>>(x, out);

    pairfix_kernel<<<256, 256>>>(x, cb, out);
    recheck_kernel<<<1024, 256>>>(x, cb, out);
}

// round 17
// speedup vs baseline: 11.2993x; 1.0157x over previous
#include <cuda_runtime.h>
#include <cuda_fp16.h>
#include <cstdint>

#define NPTS    131072
#define NBOOK   4
#define KCODES  1024
#define NCODES  4096
#define THREADS 256
#define CHUNK   32
#define CHUNKS  (NCODES / CHUNK)    // 128

// smem byte offsets (total 34KB)
#define SM_A    0               // 32KB A fp16 frags
#define SM_EX   32768           // 2KB exchange (128 rows x 4 uints)
#define SMEM_TOTAL (32768 + 2048)

__device__ float g_csq[NCODES];
__device__ float g_rowsq[NPTS];
__device__ float g_maxcsq;
__device__ int   g_npair;
__device__ int   g_nfull;
__device__ int   g_pair[NPTS * NBOOK];
__device__ int   g_full[NPTS * NBOOK];
__device__ int   g_sec[NPTS * NBOOK];
// B frags: [chunk(128)][n8grp(4)][ks(8)][lane(32)] -> {b0,b1} half2 pairs
__device__ uint2 g_bfh[CHUNKS * 4 * 8 * 32];

__device__ __forceinline__ bool lless(float v, int i, float v2, int i2) {
    return v < v2 || (v == v2 && i < i2);
}
// float -> order-preserving uint
__device__ __forceinline__ uint32_t ford(float s) {
    uint32_t b = __float_as_uint(s);
    return b ^ (uint32_t)(((int32_t)b >> 31) | 0x80000000);
}
// inverse (on quantized value)
__device__ __forceinline__ float funord(uint32_t u) {
    uint32_t q = u & 0xFFFFFC00u;
    uint32_t b = (q & 0x80000000u) ? (q ^ 0x80000000u) : ~q;
    return __uint_as_float(b);
}
// branch-free top-3 insert on packed (score|idx) uints
__device__ __forceinline__ void ins3(uint32_t& v1, uint32_t& v2, uint32_t& v3,
                                     uint32_t p) {
    uint32_t nv3 = (p < v2) ? v2 : ((p < v3) ? p : v3);
    uint32_t nv2 = (p < v1) ? v1 : ((p < v2) ? p : v2);
    v1 = (p < v1) ? p : v1;
    v2 = nv2; v3 = nv3;
}
__device__ __forceinline__ void mma16(float* d, const uint32_t* a, const uint32_t* b) {
    asm volatile(
        "mma.sync.aligned.m16n8k16.row.col.f32.f16.f16.f32 "
        "{%0,%1,%2,%3}, {%4,%5,%6,%7}, {%8,%9}, {%0,%1,%2,%3};"
        : "+f"(d[0]), "+f"(d[1]), "+f"(d[2]), "+f"(d[3])
        : "r"(a[0]), "r"(a[1]), "r"(a[2]), "r"(a[3]), "r"(b[0]), "r"(b[1]));
}
__device__ __forceinline__ uint32_t pack2(float a, float b) {
    __half2 h = __halves2half2(__float2half_rn(a), __float2half_rn(b));
    return *reinterpret_cast<uint32_t*>(&h);
}

// ||c||^2 for all 4096 codes. One warp per code.
__global__ void csq_kernel(const float* __restrict__ cb) {
    int warp = threadIdx.x >> 5, lane = threadIdx.x & 31;
    int code = blockIdx.x * 8 + warp;
    float4 v = reinterpret_cast<const float4*>(cb)[code * 32 + lane];
    float s = v.x * v.x + v.y * v.y + v.z * v.z + v.w * v.w;
#pragma unroll
    for (int o = 16; o > 0; o >>= 1) s += __shfl_xor_sync(0xffffffffu, s, o);
    if (lane == 0) g_csq[code] = s;
}

// max(csq) + reset flag counters.
__global__ void prep2_kernel() {
    __shared__ float red[256];
    float m = 0.0f;
    for (int i = threadIdx.x; i < NCODES; i += 256) m = fmaxf(m, g_csq[i]);
    red[threadIdx.x] = m;
    __syncthreads();
    for (int o = 128; o > 0; o >>= 1) {
        if (threadIdx.x < o) red[threadIdx.x] = fmaxf(red[threadIdx.x], red[threadIdx.x + o]);
        __syncthreads();
    }
    if (threadIdx.x == 0) { g_maxcsq = red[0]; g_npair = 0; g_nfull = 0; }
}

// ||x||^2 per row. One warp per row.
__global__ void rowsq_kernel(const float* __restrict__ x) {
    int warp = threadIdx.x >> 5, lane = threadIdx.x & 31;
    int row = blockIdx.x * 8 + warp;
    float4 v = reinterpret_cast<const float4*>(x)[(size_t)row * 32 + lane];
    float s = v.x * v.x + v.y * v.y + v.z * v.z + v.w * v.w;
#pragma unroll
    for (int o = 16; o > 0; o >>= 1) s += __shfl_xor_sync(0xffffffffu, s, o);
    if (lane == 0) g_rowsq[row] = s;
}

// Pre-pack B into fp16 mma fragments.
__global__ void bsplit_kernel(const float* __restrict__ cb) {
    int idx = blockIdx.x * 256 + threadIdx.x;      // 131072 total
    int lane = idx & 31;
    int ks   = (idx >> 5) & 7;
    int grp  = (idx >> 8) & 3;
    int chunk = idx >> 10;
    int code = chunk * CHUNK + grp * 8 + (lane >> 2);
    const float* cr = cb + (size_t)code * 128 + ks * 16 + (lane & 3) * 2;
    g_bfh[idx] = make_uint2(pack2(cr[0], cr[1]), pack2(cr[8], cr[9]));
}

extern __shared__ char smem[];

__global__ void __launch_bounds__(THREADS, 2)
rqk_mma(const float* __restrict__ x, float* __restrict__ out) {
    const int tid  = threadIdx.x;
    const int lane = tid & 31;
    const int warp = tid >> 5;
    const int rr   = warp & 3;     // rows rr*32..+31 (two m16 tiles)
    const int cc   = warp >> 2;    // codes cc*16..+15 (two n8 frags)
    const int qgrp = lane >> 2;
    const int th   = lane & 3;
    const int row0 = blockIdx.x * 128;

    uint32_t* EX = reinterpret_cast<uint32_t*>(smem + SM_EX);  // 4 uints/row

    // ---- A setup: load rows, fp16 pack, store m16n8k16 frag-major ----
    {
        const float4* x4 = reinterpret_cast<const float4*>(x) + (size_t)row0 * 32;
#pragma unroll
        for (int it = 0; it < 16; ++it) {
            int u = it * 256 + tid;
            int row = u >> 5, k4 = u & 31;
            float4 q = x4[row * 32 + k4];
            int tile = row >> 4, r = row & 15;
            float e[4] = {q.x, q.y, q.z, q.w};
#pragma unroll
            for (int j = 0; j < 4; ++j) {
                int k = k4 * 4 + j;
                int ks = k >> 4, kk = k & 15;
                int reg = ((kk >> 3) << 1) | (r >> 3);
                int ln  = (r & 7) * 4 + ((kk & 7) >> 1);
                int off = (((tile * 8 + ks) * 32 + ln) << 4) + (reg << 2) + ((kk & 1) << 1);
                *reinterpret_cast<__half*>(smem + SM_A + off) = __float2half_rn(e[j]);
            }
        }
    }
    __syncthreads();

    uint32_t pk1[4], pk2[4], pk3[4];
#pragma unroll
    for (int i = 0; i < 4; ++i) { pk1[i] = 0xFFFFFFFFu; pk2[i] = 0xFFFFFFFFu;
                                  pk3[i] = 0xFFFFFFFFu; }

    const float maxcsq = g_maxcsq;

    for (int ch = 0; ch < CHUNKS; ++ch) {
        // B fragments straight from L2-resident global (no smem, no barriers)
        const uint2* Bg0 = g_bfh + ((size_t)(ch * 4 + cc * 2 + 0) * 8) * 32 + lane;
        const uint2* Bg1 = g_bfh + ((size_t)(ch * 4 + cc * 2 + 1) * 8) * 32 + lane;

        float acc[2][2][4];
#pragma unroll
        for (int mt = 0; mt < 2; ++mt)
#pragma unroll
            for (int nt = 0; nt < 2; ++nt)
#pragma unroll
                for (int r = 0; r < 4; ++r) acc[mt][nt][r] = 0.0f;

#pragma unroll
        for (int ks = 0; ks < 8; ++ks) {
            uint4 a0 = *reinterpret_cast<const uint4*>(
                smem + SM_A + (((rr * 2 + 0) * 8 + ks) * 32 + lane) * 16);
            uint4 a1 = *reinterpret_cast<const uint4*>(
                smem + SM_A + (((rr * 2 + 1) * 8 + ks) * 32 + lane) * 16);
            uint2 q0 = __ldg(Bg0 + ks * 32);
            uint2 q1 = __ldg(Bg1 + ks * 32);
            uint32_t b0[2] = {q0.x, q0.y}, b1[2] = {q1.x, q1.y};
            const uint32_t* A0 = reinterpret_cast<const uint32_t*>(&a0);
            const uint32_t* A1 = reinterpret_cast<const uint32_t*>(&a1);
            mma16(acc[0][0], A0, b0); mma16(acc[1][0], A1, b0);
            mma16(acc[0][1], A0, b1); mma16(acc[1][1], A1, b1);
        }

        // ---- epilogue: packed (score|idx) branch-free top-3 ----
        int ib = (ch & 31) * CHUNK;
#pragma unroll
        for (int nt = 0; nt < 2; ++nt) {
            int n0 = cc * 16 + nt * 8 + th * 2;
            float cs0 = __ldg(&g_csq[ch * CHUNK + n0]);
            float cs1 = __ldg(&g_csq[ch * CHUNK + n0 + 1]);
            uint32_t id0 = (uint32_t)(ib + n0), id1 = id0 + 1;
#pragma unroll
            for (int mt = 0; mt < 2; ++mt)
#pragma unroll
                for (int h = 0; h < 2; ++h) {
                    int rid = mt * 2 + h;
                    float s0 = fmaf(-2.0f, acc[mt][nt][h * 2],     cs0);
                    float s1 = fmaf(-2.0f, acc[mt][nt][h * 2 + 1], cs1);
                    uint32_t p0 = (ford(s0) & 0xFFFFFC00u) | id0;
                    uint32_t p1 = (ford(s1) & 0xFFFFFC00u) | id1;
                    ins3(pk1[rid], pk2[rid], pk3[rid], p0);
                    ins3(pk1[rid], pk2[rid], pk3[rid], p1);
                }
        }

        // ---- book end: reduce lane quads, then across cc warps ----
        if ((ch & 31) == 31) {
            int book = ch >> 5;
#pragma unroll
            for (int rid = 0; rid < 4; ++rid) {
                uint32_t v1 = pk1[rid], v2 = pk2[rid], v3 = pk3[rid];
#pragma unroll
                for (int off = 1; off < 4; off <<= 1) {
                    uint32_t o1 = __shfl_xor_sync(0xffffffffu, v1, off);
                    uint32_t o2 = __shfl_xor_sync(0xffffffffu, v2, off);
                    uint32_t o3 = __shfl_xor_sync(0xffffffffu, v3, off);
                    ins3(v1, v2, v3, o1);
                    ins3(v1, v2, v3, o2);
                    ins3(v1, v2, v3, o3);
                }
                pk1[rid] = v1; pk2[rid] = v2; pk3[rid] = v3;
            }
            if (cc == 1 && th == 0) {
#pragma unroll
                for (int rid = 0; rid < 4; ++rid) {
                    int row = rr * 32 + (rid >> 1) * 16 + qgrp + (rid & 1) * 8;
                    uint32_t* e = EX + row * 4;
                    e[0] = pk1[rid]; e[1] = pk2[rid]; e[2] = pk3[rid];
                }
            }
            __syncthreads();
            if (cc == 0 && th == 0) {
#pragma unroll
                for (int rid = 0; rid < 4; ++rid) {
                    int row = rr * 32 + (rid >> 1) * 16 + qgrp + (rid & 1) * 8;
                    const uint32_t* e = EX + row * 4;
                    uint32_t v1 = pk1[rid], v2 = pk2[rid], v3 = pk3[rid];
                    ins3(v1, v2, v3, e[0]);
                    ins3(v1, v2, v3, e[1]);
                    ins3(v1, v2, v3, e[2]);
                    size_t oi = (size_t)(row0 + row) * NBOOK + book;
                    uint32_t i1 = v1 & 0x3FFu;
                    out[oi] = (float)i1;
                    // T >= 2*eps + quantization slack. eps <= 2^-9*sqrt(S2)
                    // (fp16 input rounding, Cauchy-Schwarz); packed-score
                    // quantization <= ~0.008 absolute each.
                    float S2 = __ldg(&g_rowsq[row0 + row]) * maxcsq;
                    float T = sqrtf(S2) * (1.0f / 256.0f) + 3e-2f;
                    float f1 = funord(v1), f2 = funord(v2), f3 = funord(v3);
                    if (f3 - f1 < T) {
                        int slot = atomicAdd(&g_nfull, 1);
                        g_full[slot] = (int)oi;
                    } else if (f2 - f1 < T) {
                        g_sec[oi] = (int)(v2 & 0x3FFu);
                        int slot = atomicAdd(&g_npair, 1);
                        g_pair[slot] = (int)oi;
                    }
                }
            }
            __syncthreads();   // EX reads done before next book overwrites
#pragma unroll
            for (int i = 0; i < 4; ++i) { pk1[i] = 0xFFFFFFFFu;
                                          pk2[i] = 0xFFFFFFFFu;
                                          pk3[i] = 0xFFFFFFFFu; }
        }
    }
}

// Exact fp32 compare of the approx top-2 (winner provably among them).
__global__ void pairfix_kernel(const float* __restrict__ x,
                               const float* __restrict__ cb,
                               float* __restrict__ out) {
    int nwarps = gridDim.x * (blockDim.x >> 5);
    int gw = blockIdx.x * (blockDim.x >> 5) + (threadIdx.x >> 5);
    int lane = threadIdx.x & 31;
    int n = g_npair;
    for (int it = gw; it < n; it += nwarps) {
        int w = g_pair[it];
        int row = w >> 2, book = w & 3;
        int i1 = (int)out[w];
        int i2 = g_sec[w];
        float4 a = reinterpret_cast<const float4*>(x)[(size_t)row * 32 + lane];
        float4 c1 = reinterpret_cast<const float4*>(cb)[
            ((size_t)book * KCODES + i1) * 32 + lane];
        float4 c2 = reinterpret_cast<const float4*>(cb)[
            ((size_t)book * KCODES + i2) * 32 + lane];
        float d1 = a.x * c1.x + a.y * c1.y + a.z * c1.z + a.w * c1.w;
        float d2 = a.x * c2.x + a.y * c2.y + a.z * c2.z + a.w * c2.w;
#pragma unroll
        for (int o = 16; o > 0; o >>= 1) {
            d1 += __shfl_xor_sync(0xffffffffu, d1, o);
            d2 += __shfl_xor_sync(0xffffffffu, d2, o);
        }
        if (lane == 0) {
            float s1 = fmaf(-2.0f, d1, g_csq[book * KCODES + i1]);
            float s2 = fmaf(-2.0f, d2, g_csq[book * KCODES + i2]);
            out[w] = (float)(lless(s2, i2, s1, i1) ? i2 : i1);
        }
    }
}

// Full exact fp32 rescan of items where top-3 margin was too tight.
__global__ void recheck_kernel(const float* __restrict__ x,
                               const float* __restrict__ cb,
                               float* __restrict__ out) {
    int nwarps = gridDim.x * (blockDim.x >> 5);
    int gw = blockIdx.x * (blockDim.x >> 5) + (threadIdx.x >> 5);
    int lane = threadIdx.x & 31;
    int n = g_nfull;
    for (int it = gw; it < n; it += nwarps) {
        int w = g_full[it];
        int row = w >> 2, book = w & 3;
        const float4* xr = reinterpret_cast<const float4*>(x) + (size_t)row * 32;
        float bv = 3.4e38f; int bi = 1 << 30;
        for (int j = 0; j < 32; ++j) {
            int code = j * 32 + lane;
            const float4* cr = reinterpret_cast<const float4*>(cb) +
                               ((size_t)book * KCODES + code) * 32;
            float d = 0.0f;
#pragma unroll 8
            for (int k4 = 0; k4 < 32; ++k4) {
                float4 a = xr[k4], c = cr[k4];
                d = fmaf(a.x, c.x, d); d = fmaf(a.y, c.y, d);
                d = fmaf(a.z, c.z, d); d = fmaf(a.w, c.w, d);
            }
            float s = fmaf(-2.0f, d, g_csq[book * KCODES + code]);
            if (lless(s, code, bv, bi)) { bv = s; bi = code; }
        }
#pragma unroll
        for (int off = 16; off > 0; off >>= 1) {
            float ov = __shfl_xor_sync(0xffffffffu, bv, off);
            int   oi = __shfl_xor_sync(0xffffffffu, bi, off);
            if (lless(ov, oi, bv, bi)) { bv = ov; bi = oi; }
        }
        if (lane == 0) out[w] = (float)bi;
    }
}

extern "C" void kernel_launch(void* const* d_in, const int* in_sizes, int n_in,
                              void* d_out, int out_size) {
    const float* x  = nullptr;
    const float* cb = nullptr;
    for (int i = 0; i < n_in; ++i) {
        long long s = in_sizes[i];
        if (s == 16777216LL || s == 67108864LL) x  = (const float*)d_in[i];
        if (s == 524288LL   || s == 2097152LL)  cb = (const float*)d_in[i];
    }
    if (!x)  x  = (const float*)d_in[0];
    if (!cb) cb = (const float*)d_in[n_in > 1 ? 1 : 0];
    float* out = (float*)d_out;

    csq_kernel<<<NCODES / 8, 256>>>(cb);
    prep2_kernel<<<1, 256>>>();
    bsplit_kernel<<<(CHUNKS * 4 * 8 * 32) / 256, 256>>>(cb);
    rowsq_kernel<<<NPTS / 8, 256>>>(x);

    cudaFuncSetAttribute(rqk_mma, cudaFuncAttributeMaxDynamicSharedMemorySize,
                         SMEM_TOTAL);
    rqk_mma<<<NPTS / 128, THREADS, SMEM_TOTAL>>>(x, out);

    pairfix_kernel<<<256, 256>>>(x, cb, out);
    recheck_kernel<<<1024, 256>>>(x, cb, out);
}